// round 5
// baseline (speedup 1.0000x reference)
#include <cuda_runtime.h>
#include <cstdint>

// Problem constants
#define NN 128
#define CC 64
#define TT 256
#define VV 25
#define DD 64
#define RR 16            // SE reduction dim
#define FEAT 1600        // V*D
#define ROWS (NN*TT)     // 32768
#define TTILE 8          // frames per gemm tile
#define NTILES 4         // tiles per gemm block
#define VS 26            // padded v (pad slot zero)
#define TSTR (TTILE*VS)  // 208 floats per c-row per tile
#define TILE_F (CC*TSTR) // 13312 floats per tile
#define SCATS 1664       // scatter region stride per frame (>= 24*66+63+1)
#define PS_CH 8          // preshift t-chunk

typedef unsigned long long u64;

// ---------------- scratch (device globals) -----------------------------------
__device__ float g_pooled[NN*CC];
__device__ float g_gate[NN*4];
__device__ float g_Wf[NN*CC*DD];
__device__ float g_bf[NN*DD];
__device__ float g_xs[(size_t)NN*CC*TT*VS];   // 218 MB shifted+masked x, [n][c'][t][v26]
__device__ float g_z[(size_t)NN*CC*TT*VV];    // 210 MB pre-BN z, [n][d][t][v]
__device__ float g_sum[FEAT];
__device__ float g_sumsq[FEAT];
__device__ float g_scale[FEAT];
__device__ float g_bias[FEAT];
__device__ short g_ts8[CC*VS];    // preshift gather: c'*26+v -> cp*200+vp
__device__ float g_tm[CC*VS];     // tanh(mask)+1 (0 on pad)
__device__ short g_invp[FEAT];    // y-flat g -> scatter slot (f>>6)*66 + (f&63)

// ---------------- helpers ----------------------------------------------------
__device__ __forceinline__ u64 pack2(float lo, float hi) {
    u64 r; asm("mov.b64 %0, {%1, %2};" : "=l"(r) : "f"(lo), "f"(hi)); return r;
}
__device__ __forceinline__ void unpack2(u64 v, float& lo, float& hi) {
    asm("mov.b64 {%0, %1}, %2;" : "=f"(lo), "=f"(hi) : "l"(v));
}
__device__ __forceinline__ u64 ffma2(u64 a, u64 b, u64 c) {
    u64 d; asm("fma.rn.f32x2 %0, %1, %2, %3;" : "=l"(d) : "l"(a), "l"(b), "l"(c));
    return d;
}
__device__ __forceinline__ void cp_async16(float* dst_smem, const void* src) {
    unsigned d = (unsigned)__cvta_generic_to_shared(dst_smem);
    asm volatile("cp.async.cg.shared.global [%0], [%1], 16;" :: "r"(d), "l"(src));
}
#define CP_COMMIT() asm volatile("cp.async.commit_group;")
#define CP_WAIT0()  asm volatile("cp.async.wait_group 0;")

// ---------------- kernel 0: tables + zero ------------------------------------
__global__ void table_kernel(const float* __restrict__ mask,
                             const int* __restrict__ shift_in,
                             const int* __restrict__ shift_out) {
    int tid = blockIdx.x * 256 + threadIdx.x;    // grid 32 -> 8192
    if (tid < CC*VS) {
        int c_out = tid / VS, v = tid % VS;
        if (v < VV) {
            int s = shift_in[v*CC + c_out];
            int vp = s >> 6, cp = s & 63;
            g_ts8[tid] = (short)(cp * (PS_CH*VV) + vp);
            g_tm[tid] = tanhf(mask[v*CC + c_out]) + 1.0f;
        } else { g_ts8[tid] = 0; g_tm[tid] = 0.f; }
    }
    if (tid < FEAT) {
        g_sum[tid] = 0.f; g_sumsq[tid] = 0.f;
        int g = shift_out[tid];
        g_invp[g] = (short)((tid >> 6) * 66 + (tid & 63));
    }
    if (tid < NN*CC) g_pooled[tid] = 0.f;
}

// ---------------- kernel 1: pre-shift + mask + pool --------------------------
// block = (n, tc of 8 frames); stages x0 chunk, pools it, writes shifted g_xs.
#define PS_SMEM_BYTES (CC*PS_CH*VV*4)     // 51200
__global__ void __launch_bounds__(256, 2) preshift_kernel(const float* __restrict__ x0) {
    extern __shared__ float raw[];       // [c][t8][v25]
    int bid = blockIdx.x;
    int n = bid >> 5, tc = bid & 31;
    int tid = threadIdx.x;
    const float* xb = x0 + (size_t)n * CC * (TT*VV) + tc * (PS_CH*VV);
    #pragma unroll
    for (int k = 0; k < 13; k++) {
        int i = tid + k*256;
        if (i < CC*PS_CH*VV/4) {         // 3200 float4
            int c = i / 50, q = i - c*50;
            cp_async16(raw + c*(PS_CH*VV) + q*4, xb + c*(TT*VV) + q*4);
        }
    }
    CP_COMMIT(); CP_WAIT0();
    __syncthreads();
    // pool partials
    int w = tid >> 5, l = tid & 31;
    #pragma unroll
    for (int cc = 0; cc < 8; cc++) {
        int c = w*8 + cc;
        float s = 0.f;
        #pragma unroll
        for (int i = l; i < PS_CH*VV; i += 32) s += raw[c*(PS_CH*VV) + i];
        #pragma unroll
        for (int off = 16; off; off >>= 1) s += __shfl_down_sync(0xffffffffu, s, off);
        if (l == 0) atomicAdd(&g_pooled[n*CC + c], s);
    }
    // shift-in gather + mask -> g_xs (coalesced writes)
    float* xs = g_xs + (size_t)n * (CC*TT*VS) + tc * (PS_CH*VS);
    for (int idx = tid; idx < CC*PS_CH*VS; idx += 256) {   // 13312
        int c = idx / (PS_CH*VS), r = idx - c*(PS_CH*VS);
        int t = r / VS, v = r - t*VS;
        int j = c*VS + v;
        float val = (v < VV) ? raw[g_ts8[j] + t*VV] * g_tm[j] : 0.f;
        xs[(size_t)c * (TT*VS) + r] = val;
    }
}

// ---------------- kernel 2: SE gate ------------------------------------------
__global__ void gate_kernel(const float* __restrict__ fc1_w, const float* __restrict__ fc1_b,
                            const float* __restrict__ fc2_w, const float* __restrict__ fc2_b,
                            const int* __restrict__ epoch_p) {
    int n = threadIdx.x;
    if (n >= NN) return;
    const float invP = 1.0f / (float)(TT*VV);
    float pooled[CC];
    #pragma unroll
    for (int c = 0; c < CC; c++) pooled[c] = g_pooled[n*CC + c] * invP;
    float h[RR];
    #pragma unroll
    for (int j = 0; j < RR; j++) {
        float s = fc1_b[j];
        #pragma unroll
        for (int c = 0; c < CC; c++) s += pooled[c] * fc1_w[j*CC + c];
        h[j] = s > 0.f ? s : 0.f;
    }
    float lg[4];
    #pragma unroll
    for (int k = 0; k < 4; k++) {
        float s = fc2_b[k];
        #pragma unroll
        for (int j = 0; j < RR; j++) s += h[j] * fc2_w[k*RR + j];
        lg[k] = s;
    }
    int ep = *epoch_p;
    float tao = (ep >= 60) ? 1.0f : (-(29.0f / 60.0f) * (float)ep + 30.0f);
    float inv = 1.0f / tao;
    float m = lg[0];
    #pragma unroll
    for (int k = 1; k < 4; k++) m = fmaxf(m, lg[k]);
    float e[4], sum = 0.f;
    #pragma unroll
    for (int k = 0; k < 4; k++) { e[k] = __expf((lg[k] - m) * inv); sum += e[k]; }
    float r = 1.0f / sum;
    #pragma unroll
    for (int k = 0; k < 4; k++) g_gate[n*4 + k] = e[k] * r;
}

// ---------------- kernel 3: fused per-sample weights -------------------------
__global__ void prepw_kernel(const float* __restrict__ W, const float* __restrict__ b) {
    int n = blockIdx.x;
    int tid = threadIdx.x;
    float g0 = g_gate[n*4+0], g1 = g_gate[n*4+1], g2 = g_gate[n*4+2], g3 = g_gate[n*4+3];
    for (int i = tid; i < CC*DD; i += 256)
        g_Wf[n*CC*DD + i] = g0*W[i] + g1*W[CC*DD + i] + g2*W[2*CC*DD + i] + g3*W[3*CC*DD + i];
    if (tid < DD)
        g_bf[n*DD + tid] = g0*b[tid] + g1*b[DD+tid] + g2*b[2*DD+tid] + g3*b[3*DD+tid];
}

// ---------------- kernel 4: pipelined GEMM + scatter + stats -----------------
// 1024 blocks = (n, q8); 4 tiles of 8 frames. 8 warps; warp = frame; lane = d-pair.
#define GEMM_SMEM_BYTES ((TILE_F + TTILE*SCATS + DD)*4 + FEAT*2 + 64)

__global__ void __launch_bounds__(256, 2) gemm_kernel() {
    extern __shared__ float sm[];
    float* raw  = sm;                       // [c][t8][v26]  13312
    float* scat = raw + TILE_F;             // 8 x 1664
    float* bfs  = scat + TTILE*SCATS;       // [64]
    short* invs = (short*)(bfs + DD);       // [1600]

    int bid = blockIdx.x;
    int n = bid >> 3, q8 = bid & 7;
    int tid = threadIdx.x;
    int w = tid >> 5, l = tid & 31;
    int d0 = 2*l;

    for (int f = tid; f < FEAT; f += 256) invs[f] = g_invp[f];
    if (tid < DD) bfs[tid] = g_bf[n*DD + tid];

    const float* xsb = g_xs + (size_t)n * (CC*TT*VS) + q8 * (32*VS);
    // prefetch tile 0
    #pragma unroll
    for (int k = 0; k < 13; k++) {
        int i = tid + k*256;                // 3328 float4
        int c = i / 52, q = i - c*52;
        cp_async16(raw + c*TSTR + q*4, xsb + (size_t)c*(TT*VS) + q*4);
    }
    CP_COMMIT();

    float rsum[7], rsq[7];
    #pragma unroll
    for (int k = 0; k < 7; k++) { rsum[k] = 0.f; rsq[k] = 0.f; }

    float b0 = 0.f, b1 = 0.f;   // read after first sync
    bool bload = false;

    const float* Wg = g_Wf + (size_t)n * (CC*DD) + d0;

    for (int it = 0; it < NTILES; it++) {
        int t0 = q8*32 + it*TTILE;
        CP_WAIT0();
        __syncthreads();                    // raw ready; prev scat consumed
        if (!bload) { b0 = bfs[d0]; b1 = bfs[d0+1]; bload = true; }

        // ---- FFMA2 mainloop ----
        u64 acc0[13], acc1[13];
        {
            u64 bb0 = pack2(b0, b0), bb1 = pack2(b1, b1);
            #pragma unroll
            for (int vp = 0; vp < 13; vp++) { acc0[vp] = bb0; acc1[vp] = bb1; }
        }
        #pragma unroll
        for (int cb = 0; cb < CC; cb += 8) {
            float2 wv[8];
            #pragma unroll
            for (int i = 0; i < 8; i++) wv[i] = *(const float2*)(Wg + (cb+i)*DD);
            #pragma unroll
            for (int i = 0; i < 8; i++) {
                u64 s0 = pack2(wv[i].x, wv[i].x);
                u64 s1 = pack2(wv[i].y, wv[i].y);
                const u64* ar = (const u64*)(raw + (cb+i)*TSTR + w*VS);
                #pragma unroll
                for (int vp = 0; vp < 13; vp++) {
                    u64 a2 = ar[vp];
                    acc0[vp] = ffma2(a2, s0, acc0[vp]);
                    acc1[vp] = ffma2(a2, s1, acc1[vp]);
                }
            }
        }

        // ---- scatter into own frame region (permuted slot layout v*66+d) ----
        float* sw = scat + w * SCATS;
        #pragma unroll
        for (int vp = 0; vp < 13; vp++) {
            float a0, a1, c0, c1;
            unpack2(acc0[vp], a0, a1);
            unpack2(acc1[vp], c0, c1);
            int g0 = (2*vp)*DD + d0;
            sw[invs[g0]]     = a0;
            sw[invs[g0 + 1]] = c0;
            if (2*vp + 1 < VV) {
                sw[invs[g0 + DD]]     = a1;
                sw[invs[g0 + DD + 1]] = c1;
            }
        }
        __syncthreads();                    // all frames scattered; raw free

        // prefetch next tile (overlaps stats + z-store)
        if (it + 1 < NTILES) {
            const float* src = xsb + (size_t)(it+1) * TSTR;
            #pragma unroll
            for (int k = 0; k < 13; k++) {
                int i = tid + k*256;
                int c = i / 52, q = i - c*52;
                cp_async16(raw + c*TSTR + q*4, src + (size_t)c*(TT*VS) + q*4);
            }
            CP_COMMIT();
        }

        // ---- BN stats: thread owns fixed f-slots ----
        #pragma unroll
        for (int k = 0; k < 7; k++) {
            int f = tid + k*256;
            if (f < FEAT) {
                int pa = (f >> 6) * 66 + (f & 63);
                float s = 0.f, q = 0.f;
                #pragma unroll
                for (int w8 = 0; w8 < 8; w8++) {
                    float v = scat[w8*SCATS + pa];
                    s += v; q += v*v;
                }
                rsum[k] += s; rsq[k] += q;
            }
        }
        // ---- z-store: warp covers d = w*8..w*8+7, lanes over v (coalesced) ----
        if (l < VV) {
            float* zb = g_z + (size_t)n * (CC*TT*VV) + (size_t)t0 * VV + l;
            #pragma unroll
            for (int dd = 0; dd < 8; dd++) {
                int d = w*8 + dd;
                #pragma unroll
                for (int tl = 0; tl < 8; tl++) {
                    zb[(size_t)d*(TT*VV) + tl*VV] = scat[tl*SCATS + l*66 + d];
                }
            }
        }
        // loop-top sync protects scat reuse
    }
    __syncthreads();
    #pragma unroll
    for (int k = 0; k < 7; k++) {
        int f = tid + k*256;
        if (f < FEAT) {
            atomicAdd(&g_sum[f], rsum[k]);
            atomicAdd(&g_sumsq[f], rsq[k]);
        }
    }
}

// ---------------- kernel 5: finalize BN params -------------------------------
__global__ void finalize_kernel(const float* __restrict__ gamma,
                                const float* __restrict__ beta) {
    int f = blockIdx.x * 256 + threadIdx.x;
    if (f >= FEAT) return;
    const float invn = 1.0f / (float)ROWS;
    float mu = g_sum[f] * invn;
    float var = g_sumsq[f] * invn - mu * mu;
    float sc = gamma[f] * rsqrtf(var + 1e-5f);
    g_scale[f] = sc;
    g_bias[f] = beta[f] - mu * sc;
}

// ---------------- kernel 6: elementwise BN + residual + relu -----------------
__global__ void __launch_bounds__(256) final_kernel(const float* __restrict__ x0,
                                                    float* __restrict__ out) {
    __shared__ float sc[VV], bi[VV];
    int b = blockIdx.x;
    int n = b >> 6, d = b & 63;
    int tid = threadIdx.x;
    if (tid < VV) {
        sc[tid] = g_scale[tid*DD + d];
        bi[tid] = g_bias[tid*DD + d];
    }
    __syncthreads();
    size_t base = (size_t)n * (CC*TT*VV) + (size_t)d * (TT*VV);
    const float4* zp = (const float4*)(g_z + base);
    const float4* xp = (const float4*)(x0 + base);
    float4* op = (float4*)(out + base);
    #pragma unroll
    for (int k = 0; k < 7; k++) {
        int q = tid + k*256;
        if (q < (TT*VV)/4) {
            int e = q*4;
            int v0 = e - (e/25)*25;
            float4 z = zp[q], x = xp[q], o;
            #pragma unroll
            for (int j = 0; j < 4; j++) {
                int v = v0 + j; if (v >= VV) v -= VV;
                float val = ((const float*)&z)[j] * sc[v] + bi[v] + ((const float*)&x)[j];
                ((float*)&o)[j] = val > 0.f ? val : 0.f;
            }
            op[q] = o;
        }
    }
}

// ---------------- launcher ---------------------------------------------------
extern "C" void kernel_launch(void* const* d_in, const int* in_sizes, int n_in,
                              void* d_out, int out_size) {
    const float* x0       = (const float*)d_in[0];
    const int*   epoch    = (const int*)  d_in[1];
    const float* fc1_w    = (const float*)d_in[2];
    const float* fc1_b    = (const float*)d_in[3];
    const float* fc2_w    = (const float*)d_in[4];
    const float* fc2_b    = (const float*)d_in[5];
    const float* W        = (const float*)d_in[6];
    const float* b        = (const float*)d_in[7];
    const float* mask     = (const float*)d_in[8];
    const float* gamma    = (const float*)d_in[9];
    const float* beta     = (const float*)d_in[10];
    const int*   shift_in = (const int*)  d_in[11];
    const int*   shift_out= (const int*)  d_in[12];
    float* out = (float*)d_out;

    cudaFuncSetAttribute(preshift_kernel, cudaFuncAttributeMaxDynamicSharedMemorySize, PS_SMEM_BYTES);
    cudaFuncSetAttribute(gemm_kernel, cudaFuncAttributeMaxDynamicSharedMemorySize, GEMM_SMEM_BYTES);

    table_kernel<<<32, 256>>>(mask, shift_in, shift_out);
    preshift_kernel<<<NN*32, 256, PS_SMEM_BYTES>>>(x0);
    gate_kernel<<<1, 128>>>(fc1_w, fc1_b, fc2_w, fc2_b, epoch);
    prepw_kernel<<<NN, 256>>>(W, b);
    gemm_kernel<<<NN*8, 256, GEMM_SMEM_BYTES>>>();
    finalize_kernel<<<(FEAT + 255)/256, 256>>>(gamma, beta);
    final_kernel<<<NN*CC, 256>>>(x0, out);
}